// round 10
// baseline (speedup 1.0000x reference)
#include <cuda_runtime.h>
#include <math.h>

namespace {

constexpr int EMBED     = 20;
constexpr int THREADS   = 256;   // conv CTA
constexpr int FEAT      = 560;
constexpr int BATCH_MAX = 16384;

typedef unsigned long long ull;

// ---------------- packed f32x2 helpers (Blackwell FFMA2) ----------------
__device__ __forceinline__ ull pack2(float a, float b) {
  ull r;
  asm("mov.b64 %0, {%1, %2};" : "=l"(r) : "f"(a), "f"(b));
  return r;
}
__device__ __forceinline__ void unpack2(ull v, float& a, float& b) {
  asm("mov.b64 {%0, %1}, %2;" : "=f"(a), "=f"(b) : "l"(v));
}
__device__ __forceinline__ ull fma2(ull a, ull b, ull c) {
  ull d;
  asm("fma.rn.f32x2 %0, %1, %2, %3;" : "=l"(d) : "l"(a), "l"(b), "l"(c));
  return d;
}

// ---------------- global scratch ----------------
__device__ float  g_feat[FEAT * BATCH_MAX];   // transposed [feat][B]
__device__ float2 g_w1p[FEAT * 32];           // [i][colpair]=(W1[2c][i],W1[2c+1][i])

struct ConvParams {
  const float* seq[7];
  const float* Wk[5];
  int B;
};
struct MlpParams {
  const float* lin1_w;
  const float* lin1_b;
  const float* lin2_w;
  const float* lin2_b;
  float* out;
  int B;
};

// smem: x tile only, [c*L+l][33] float2 = (x_b, x_{b+32}); max L = 18
constexpr int CONV_SMEM_BYTES = EMBED * 18 * 33 * 8;   // 95040

// ======================= CONV (R5 verbatim — measured ~357us) ===========
template<int L, int K, int T0, int T1>
__device__ __forceinline__ void conv_chunk(const ull* __restrict__ sXu,
                                           const float* __restrict__ wg,
                                           int lane, float& m0, float& m1) {
  constexpr int PAD = (K - 1) / 2;
  constexpr int XLO = (T0 - PAD > 0) ? (T0 - PAD) : 0;
  constexpr int XHI = (T1 + PAD < L) ? (T1 + PAD) : L;   // exclusive
  constexpr int NX  = XHI - XLO;
  constexpr int NT  = T1 - T0;
  ull acc[NT];
  #pragma unroll
  for (int t = 0; t < NT; ++t) acc[t] = 0ULL;
  #pragma unroll 2
  for (int c = 0; c < EMBED; ++c) {
    ull xx[NX];
    #pragma unroll
    for (int l = 0; l < NX; ++l)
      xx[l] = sXu[(c * L + XLO + l) * 33 + lane];        // LDS.64, pairs
    ull wt[K];
    #pragma unroll
    for (int j = 0; j < K; ++j) {
      const float wv = __ldg(wg + c * K + j);            // warp-uniform, L1
      wt[j] = pack2(wv, wv);
    }
    #pragma unroll
    for (int t = T0; t < T1; ++t) {
      #pragma unroll
      for (int j = 0; j < K; ++j) {
        const int xi = t + j - PAD;                      // compile-time pred
        if (xi >= 0 && xi < L)
          acc[t - T0] = fma2(xx[xi - XLO], wt[j], acc[t - T0]);
      }
    }
  }
  #pragma unroll
  for (int t = 0; t < NT; ++t) {
    float a, b; unpack2(acc[t], a, b);
    m0 = fmaxf(m0, a); m1 = fmaxf(m1, b);                // relu+gmax
  }
}

template<int L, int K>
__device__ __forceinline__ void conv_all(const ull* __restrict__ sXu,
                                         const float* __restrict__ wg,
                                         int lane, float& m0, float& m1) {
  if constexpr (L <= 9) {
    conv_chunk<L, K, 0, L>(sXu, wg, lane, m0, m1);
  } else if constexpr (L <= 12) {
    conv_chunk<L, K, 0, 6>(sXu, wg, lane, m0, m1);
    conv_chunk<L, K, 6, L>(sXu, wg, lane, m0, m1);
  } else {
    conv_chunk<L, K, 0, 6>(sXu, wg, lane, m0, m1);
    conv_chunk<L, K, 6, 12>(sXu, wg, lane, m0, m1);
    conv_chunk<L, K, 12, L>(sXu, wg, lane, m0, m1);
  }
}

template<int L, int S>
__device__ void do_seq(const ConvParams& p, float2* sX2,
                       int tid, int lane, int w, int bbase) {
  const float* xg = p.seq[S];
  constexpr int CL = EMBED * L;
  for (int idx = tid; idx < CL * 32; idx += THREADS) {
    const int bp  = idx / CL;
    const int rem = idx - bp * CL;
    const int b0  = min(bbase + bp, p.B - 1);
    const int b1  = min(b0 + 32, p.B - 1);
    sX2[rem * 33 + bp] = make_float2(xg[(size_t)b0 * CL + rem] * 0.2f,
                                     xg[(size_t)b1 * CL + rem] * 0.2f);
  }
  __syncthreads();
  const ull* sXu = (const ull*)sX2;
  const int bg0 = min(bbase + lane, p.B - 1);
  const int bg1 = min(bg0 + 32, p.B - 1);

  #pragma unroll
  for (int fi = 0; fi < 2; ++fi) {
    const int f = 2 * w + fi;
    {
      float m0 = 0.f, m1 = 0.f;
      conv_all<L, 1>(sXu, p.Wk[0] + ((size_t)S * 16 + f) * EMBED * 1, lane, m0, m1);
      g_feat[(size_t)(S * 80 + 0 + f) * p.B + bg0] = m0;
      g_feat[(size_t)(S * 80 + 0 + f) * p.B + bg1] = m1;
    }
    {
      float m0 = 0.f, m1 = 0.f;
      conv_all<L, 3>(sXu, p.Wk[1] + ((size_t)S * 16 + f) * EMBED * 3, lane, m0, m1);
      g_feat[(size_t)(S * 80 + 16 + f) * p.B + bg0] = m0;
      g_feat[(size_t)(S * 80 + 16 + f) * p.B + bg1] = m1;
    }
    {
      float m0 = 0.f, m1 = 0.f;
      conv_all<L, 5>(sXu, p.Wk[2] + ((size_t)S * 16 + f) * EMBED * 5, lane, m0, m1);
      g_feat[(size_t)(S * 80 + 32 + f) * p.B + bg0] = m0;
      g_feat[(size_t)(S * 80 + 32 + f) * p.B + bg1] = m1;
    }
    {
      float m0 = 0.f, m1 = 0.f;
      conv_all<L, 7>(sXu, p.Wk[3] + ((size_t)S * 16 + f) * EMBED * 7, lane, m0, m1);
      g_feat[(size_t)(S * 80 + 48 + f) * p.B + bg0] = m0;
      g_feat[(size_t)(S * 80 + 48 + f) * p.B + bg1] = m1;
    }
    {
      float m0 = 0.f, m1 = 0.f;
      conv_all<L, 9>(sXu, p.Wk[4] + ((size_t)S * 16 + f) * EMBED * 9, lane, m0, m1);
      g_feat[(size_t)(S * 80 + 64 + f) * p.B + bg0] = m0;
      g_feat[(size_t)(S * 80 + 64 + f) * p.B + bg1] = m1;
    }
  }
}

__global__ __launch_bounds__(THREADS, 2) void conv_kernel(ConvParams p) {
  extern __shared__ float smem[];
  float2* sX2 = (float2*)smem;
  const int tid   = threadIdx.x;
  const int lane  = tid & 31;
  const int w     = tid >> 5;          // warp -> filter pair (2w, 2w+1)
  const int bbase = blockIdx.x * 64;   // 64 batch per CTA (paired)
  switch (blockIdx.y) {
    case 0: do_seq<12, 0>(p, sX2, tid, lane, w, bbase); break;
    case 1: do_seq< 7, 1>(p, sX2, tid, lane, w, bbase); break;
    case 2: do_seq< 8, 2>(p, sX2, tid, lane, w, bbase); break;
    case 3: do_seq<16, 3>(p, sX2, tid, lane, w, bbase); break;
    case 4: do_seq< 6, 4>(p, sX2, tid, lane, w, bbase); break;
    case 5: do_seq< 7, 5>(p, sX2, tid, lane, w, bbase); break;
    case 6: do_seq<18, 6>(p, sX2, tid, lane, w, bbase); break;
  }
}

// ---------------- merged prep: W1 pre-pack (single launch) --------------
__global__ void prep_kernel(const float* __restrict__ w1) {
  const int idx = blockIdx.x * 256 + threadIdx.x;
  if (idx < FEAT * 32) {
    const int i   = idx >> 5;
    const int col = idx & 31;
    g_w1p[idx] = make_float2(w1[(size_t)(2 * col) * FEAT + i],
                             w1[(size_t)(2 * col + 1) * FEAT + i]);
  }
}

// ====== MLP v6: 64 batch/CTA, 256 thr, 3 CTA/SM, split-K halves =========
// warp (h,g): h = feature half (280), g = 16 hidden cols (8 col-pairs).
constexpr int MTHREADS = 256;
constexpr int MLP_SMEM_BYTES = 2 * 64 * 65 * 4;   // 33280

__global__ __launch_bounds__(MTHREADS, 3) void mlp_kernel(MlpParams p) {
  extern __shared__ float smem[];
  float* sP1 = smem;             // [64][65] h=1 partials
  float* sH  = smem + 64 * 65;   // [64][65] sigmoid outputs
  const int tid  = threadIdx.x;
  const int lane = tid & 31;
  const int wid  = tid >> 5;     // 0..7
  const int h    = wid >> 2;     // feature half
  const int g    = wid & 3;      // 16-col group
  const int bbase = blockIdx.x * 64;
  const bool full = (bbase + 64 <= p.B);

  ull acc[8][2];                 // [col pair within group][batch elem]
  #pragma unroll
  for (int cp = 0; cp < 8; ++cp) {
    const ull bia = (h == 0)
      ? pack2(p.lin1_b[g * 16 + 2 * cp], p.lin1_b[g * 16 + 2 * cp + 1])
      : 0ULL;
    acc[cp][0] = bia; acc[cp][1] = bia;
  }

  const float4* wbase = (const float4*)(g_w1p);   // 16 float4 per feature
  const int i0 = h * 280;

  for (int oo = 0; oo < 280; oo += 4) {
    float2 fb[4];
    if (full) {
      #pragma unroll
      for (int k = 0; k < 4; ++k)
        fb[k] = __ldg((const float2*)(g_feat + (size_t)(i0 + oo + k) * p.B
                                      + bbase + lane * 2));
    } else {
      #pragma unroll
      for (int k = 0; k < 4; ++k) {
        const int ba = min(bbase + lane * 2, p.B - 1);
        const int bbq = min(bbase + lane * 2 + 1, p.B - 1);
        fb[k] = make_float2(g_feat[(size_t)(i0 + oo + k) * p.B + ba],
                            g_feat[(size_t)(i0 + oo + k) * p.B + bbq]);
      }
    }
    #pragma unroll
    for (int k = 0; k < 4; ++k) {
      const int i = i0 + oo + k;
      const ull ff0 = pack2(fb[k].x, fb[k].x);
      const ull ff1 = pack2(fb[k].y, fb[k].y);
      #pragma unroll
      for (int q = 0; q < 4; ++q) {
        const float4 wv = wbase[i * 16 + g * 4 + q];   // uniform, L1-hot
        const ull wA = pack2(wv.x, wv.y);
        const ull wB = pack2(wv.z, wv.w);
        acc[2 * q][0]     = fma2(ff0, wA, acc[2 * q][0]);
        acc[2 * q][1]     = fma2(ff1, wA, acc[2 * q][1]);
        acc[2 * q + 1][0] = fma2(ff0, wB, acc[2 * q + 1][0]);
        acc[2 * q + 1][1] = fma2(ff1, wB, acc[2 * q + 1][1]);
      }
    }
  }

  if (h == 1) {
    #pragma unroll
    for (int bi = 0; bi < 2; ++bi)
      #pragma unroll
      for (int cp = 0; cp < 8; ++cp) {
        float a, bb; unpack2(acc[cp][bi], a, bb);
        sP1[(lane * 2 + bi) * 65 + g * 16 + 2 * cp]     = a;
        sP1[(lane * 2 + bi) * 65 + g * 16 + 2 * cp + 1] = bb;
      }
  }
  __syncthreads();
  if (h == 0) {
    #pragma unroll
    for (int bi = 0; bi < 2; ++bi)
      #pragma unroll
      for (int cp = 0; cp < 8; ++cp) {
        float a, bb; unpack2(acc[cp][bi], a, bb);
        a  += sP1[(lane * 2 + bi) * 65 + g * 16 + 2 * cp];
        bb += sP1[(lane * 2 + bi) * 65 + g * 16 + 2 * cp + 1];
        sH[(lane * 2 + bi) * 65 + g * 16 + 2 * cp]     = 1.f / (1.f + __expf(-a));
        sH[(lane * 2 + bi) * 65 + g * 16 + 2 * cp + 1] = 1.f / (1.f + __expf(-bb));
      }
  }
  __syncthreads();

  if (tid < 64) {
    const int bgo = bbase + tid;
    if (bgo < p.B) {
      float o = p.lin2_b[0];
      #pragma unroll
      for (int j = 0; j < 64; ++j)
        o = fmaf(sH[tid * 65 + j], __ldg(p.lin2_w + j), o);
      p.out[bgo] = o;
    }
  }
}

} // namespace

extern "C" void kernel_launch(void* const* d_in, const int* in_sizes, int n_in,
                              void* d_out, int out_size) {
  ConvParams cp;
  for (int i = 0; i < 7; ++i) cp.seq[i] = (const float*)d_in[i];
  for (int j = 0; j < 5; ++j) cp.Wk[j] = (const float*)d_in[7 + j];
  cp.B = out_size;

  MlpParams mp;
  mp.lin1_w = (const float*)d_in[12];
  mp.lin1_b = (const float*)d_in[13];
  mp.lin2_w = (const float*)d_in[14];
  mp.lin2_b = (const float*)d_in[15];
  mp.out = (float*)d_out;
  mp.B   = out_size;

  static bool attr_set = false;
  if (!attr_set) {
    cudaFuncSetAttribute(conv_kernel,
                         cudaFuncAttributeMaxDynamicSharedMemorySize, CONV_SMEM_BYTES);
    cudaFuncSetAttribute(mlp_kernel,
                         cudaFuncAttributeMaxDynamicSharedMemorySize, MLP_SMEM_BYTES);
    attr_set = true;
  }

  const int tiles64 = (cp.B + 63) / 64;
  prep_kernel<<<(FEAT * 32 + 255) / 256, 256>>>(mp.lin1_w);
  dim3 cgrid(tiles64, 7);
  conv_kernel<<<cgrid, THREADS, CONV_SMEM_BYTES>>>(cp);
  mlp_kernel<<<tiles64, MTHREADS, MLP_SMEM_BYTES>>>(mp);
}

// round 11
// speedup vs baseline: 1.0461x; 1.0461x over previous
#include <cuda_runtime.h>
#include <math.h>

namespace {

constexpr int EMBED     = 20;
constexpr int THREADS   = 256;   // conv CTA
constexpr int FEAT      = 560;
constexpr int BATCH_MAX = 16384;

typedef unsigned long long ull;

// ---------------- packed f32x2 helpers (Blackwell FFMA2) ----------------
__device__ __forceinline__ ull pack2(float a, float b) {
  ull r;
  asm("mov.b64 %0, {%1, %2};" : "=l"(r) : "f"(a), "f"(b));
  return r;
}
__device__ __forceinline__ void unpack2(ull v, float& a, float& b) {
  asm("mov.b64 {%0, %1}, %2;" : "=f"(a), "=f"(b) : "l"(v));
}
__device__ __forceinline__ ull fma2(ull a, ull b, ull c) {
  ull d;
  asm("fma.rn.f32x2 %0, %1, %2, %3;" : "=l"(d) : "l"(a), "l"(b), "l"(c));
  return d;
}

// ---------------- global scratch ----------------
__device__ float  g_feat[FEAT * BATCH_MAX];   // transposed [feat][B]
__device__ float2 g_w1p[FEAT * 32];           // [i][colpair]=(W1[2c][i],W1[2c+1][i])

struct ConvParams {
  const float* seq[7];
  const float* Wk[5];
  int B;
};
struct MlpParams {
  const float* lin1_w;
  const float* lin1_b;
  const float* lin2_w;
  const float* lin2_b;
  float* out;
  int B;
};

// smem: x tile only, [c*L+l][33] float2 = (x_b, x_{b+32}); max L = 18
constexpr int CONV_SMEM_BYTES = EMBED * 18 * 33 * 8;   // 95040

// ======================= CONV (R5 verbatim — measured ~357us) ===========
template<int L, int K, int T0, int T1>
__device__ __forceinline__ void conv_chunk(const ull* __restrict__ sXu,
                                           const float* __restrict__ wg,
                                           int lane, float& m0, float& m1) {
  constexpr int PAD = (K - 1) / 2;
  constexpr int XLO = (T0 - PAD > 0) ? (T0 - PAD) : 0;
  constexpr int XHI = (T1 + PAD < L) ? (T1 + PAD) : L;   // exclusive
  constexpr int NX  = XHI - XLO;
  constexpr int NT  = T1 - T0;
  ull acc[NT];
  #pragma unroll
  for (int t = 0; t < NT; ++t) acc[t] = 0ULL;
  #pragma unroll 2
  for (int c = 0; c < EMBED; ++c) {
    ull xx[NX];
    #pragma unroll
    for (int l = 0; l < NX; ++l)
      xx[l] = sXu[(c * L + XLO + l) * 33 + lane];        // LDS.64, pairs
    ull wt[K];
    #pragma unroll
    for (int j = 0; j < K; ++j) {
      const float wv = __ldg(wg + c * K + j);            // warp-uniform, L1
      wt[j] = pack2(wv, wv);
    }
    #pragma unroll
    for (int t = T0; t < T1; ++t) {
      #pragma unroll
      for (int j = 0; j < K; ++j) {
        const int xi = t + j - PAD;                      // compile-time pred
        if (xi >= 0 && xi < L)
          acc[t - T0] = fma2(xx[xi - XLO], wt[j], acc[t - T0]);
      }
    }
  }
  #pragma unroll
  for (int t = 0; t < NT; ++t) {
    float a, b; unpack2(acc[t], a, b);
    m0 = fmaxf(m0, a); m1 = fmaxf(m1, b);                // relu+gmax
  }
}

template<int L, int K>
__device__ __forceinline__ void conv_all(const ull* __restrict__ sXu,
                                         const float* __restrict__ wg,
                                         int lane, float& m0, float& m1) {
  if constexpr (L <= 9) {
    conv_chunk<L, K, 0, L>(sXu, wg, lane, m0, m1);
  } else if constexpr (L <= 12) {
    conv_chunk<L, K, 0, 6>(sXu, wg, lane, m0, m1);
    conv_chunk<L, K, 6, L>(sXu, wg, lane, m0, m1);
  } else {
    conv_chunk<L, K, 0, 6>(sXu, wg, lane, m0, m1);
    conv_chunk<L, K, 6, 12>(sXu, wg, lane, m0, m1);
    conv_chunk<L, K, 12, L>(sXu, wg, lane, m0, m1);
  }
}

template<int L, int S>
__device__ void do_seq(const ConvParams& p, float2* sX2,
                       int tid, int lane, int w, int bbase) {
  const float* xg = p.seq[S];
  constexpr int CL = EMBED * L;
  for (int idx = tid; idx < CL * 32; idx += THREADS) {
    const int bp  = idx / CL;
    const int rem = idx - bp * CL;
    const int b0  = min(bbase + bp, p.B - 1);
    const int b1  = min(b0 + 32, p.B - 1);
    sX2[rem * 33 + bp] = make_float2(xg[(size_t)b0 * CL + rem] * 0.2f,
                                     xg[(size_t)b1 * CL + rem] * 0.2f);
  }
  __syncthreads();
  const ull* sXu = (const ull*)sX2;
  const int bg0 = min(bbase + lane, p.B - 1);
  const int bg1 = min(bg0 + 32, p.B - 1);

  #pragma unroll
  for (int fi = 0; fi < 2; ++fi) {
    const int f = 2 * w + fi;
    {
      float m0 = 0.f, m1 = 0.f;
      conv_all<L, 1>(sXu, p.Wk[0] + ((size_t)S * 16 + f) * EMBED * 1, lane, m0, m1);
      g_feat[(size_t)(S * 80 + 0 + f) * p.B + bg0] = m0;
      g_feat[(size_t)(S * 80 + 0 + f) * p.B + bg1] = m1;
    }
    {
      float m0 = 0.f, m1 = 0.f;
      conv_all<L, 3>(sXu, p.Wk[1] + ((size_t)S * 16 + f) * EMBED * 3, lane, m0, m1);
      g_feat[(size_t)(S * 80 + 16 + f) * p.B + bg0] = m0;
      g_feat[(size_t)(S * 80 + 16 + f) * p.B + bg1] = m1;
    }
    {
      float m0 = 0.f, m1 = 0.f;
      conv_all<L, 5>(sXu, p.Wk[2] + ((size_t)S * 16 + f) * EMBED * 5, lane, m0, m1);
      g_feat[(size_t)(S * 80 + 32 + f) * p.B + bg0] = m0;
      g_feat[(size_t)(S * 80 + 32 + f) * p.B + bg1] = m1;
    }
    {
      float m0 = 0.f, m1 = 0.f;
      conv_all<L, 7>(sXu, p.Wk[3] + ((size_t)S * 16 + f) * EMBED * 7, lane, m0, m1);
      g_feat[(size_t)(S * 80 + 48 + f) * p.B + bg0] = m0;
      g_feat[(size_t)(S * 80 + 48 + f) * p.B + bg1] = m1;
    }
    {
      float m0 = 0.f, m1 = 0.f;
      conv_all<L, 9>(sXu, p.Wk[4] + ((size_t)S * 16 + f) * EMBED * 9, lane, m0, m1);
      g_feat[(size_t)(S * 80 + 64 + f) * p.B + bg0] = m0;
      g_feat[(size_t)(S * 80 + 64 + f) * p.B + bg1] = m1;
    }
  }
}

__global__ __launch_bounds__(THREADS, 2) void conv_kernel(ConvParams p) {
  extern __shared__ float smem[];
  float2* sX2 = (float2*)smem;
  const int tid   = threadIdx.x;
  const int lane  = tid & 31;
  const int w     = tid >> 5;          // warp -> filter pair (2w, 2w+1)
  const int bbase = blockIdx.x * 64;   // 64 batch per CTA (paired)
  switch (blockIdx.y) {
    case 0: do_seq<12, 0>(p, sX2, tid, lane, w, bbase); break;
    case 1: do_seq< 7, 1>(p, sX2, tid, lane, w, bbase); break;
    case 2: do_seq< 8, 2>(p, sX2, tid, lane, w, bbase); break;
    case 3: do_seq<16, 3>(p, sX2, tid, lane, w, bbase); break;
    case 4: do_seq< 6, 4>(p, sX2, tid, lane, w, bbase); break;
    case 5: do_seq< 7, 5>(p, sX2, tid, lane, w, bbase); break;
    case 6: do_seq<18, 6>(p, sX2, tid, lane, w, bbase); break;
  }
}

// ---------------- prep: W1 pre-pack ----------------
__global__ void prep_kernel(const float* __restrict__ w1) {
  const int idx = blockIdx.x * 256 + threadIdx.x;
  if (idx < FEAT * 32) {
    const int i   = idx >> 5;
    const int col = idx & 31;
    g_w1p[idx] = make_float2(w1[(size_t)(2 * col) * FEAT + i],
                             w1[(size_t)(2 * col + 1) * FEAT + i]);
  }
}

// ====== MLP v7: 64 batch/CTA (grid 256), 512 thr, v5 warp shape ==========
// warp (h,g): h = feature half (280 feats), g = 8 cols (4 colpairs).
// thread: 2 batch elems (float2 feature loads).
constexpr int MTHREADS = 512;
constexpr int MLP_SMEM_BYTES = 2 * 64 * 65 * 4;   // 33280

__global__ __launch_bounds__(MTHREADS, 2) void mlp_kernel(MlpParams p) {
  extern __shared__ float smem[];
  float* sP1 = smem;             // [64][65] h=1 partials
  float* sH  = smem + 64 * 65;   // [64][65] sigmoid outputs
  const int tid  = threadIdx.x;
  const int lane = tid & 31;
  const int wid  = tid >> 5;     // 0..15
  const int h    = wid >> 3;     // feature half
  const int g    = wid & 7;      // col group (cols 8g..8g+7)
  const int bbase = blockIdx.x * 64;
  const bool full = (bbase + 64 <= p.B);

  ull acc[4][2];                 // [colpair][batch elem]
  #pragma unroll
  for (int cp = 0; cp < 4; ++cp) {
    const ull bia = (h == 0)
      ? pack2(p.lin1_b[g * 8 + 2 * cp], p.lin1_b[g * 8 + 2 * cp + 1])
      : 0ULL;
    acc[cp][0] = bia; acc[cp][1] = bia;
  }

  const float4* wbase = (const float4*)(g_w1p);   // 16 float4 per feature
  const int i0 = h * 280;

  for (int oo = 0; oo < 280; oo += 4) {
    float2 fb[4];
    if (full) {
      #pragma unroll
      for (int k = 0; k < 4; ++k)
        fb[k] = __ldg((const float2*)(g_feat + (size_t)(i0 + oo + k) * p.B
                                      + bbase + lane * 2));
    } else {
      #pragma unroll
      for (int k = 0; k < 4; ++k) {
        const int ba = min(bbase + lane * 2, p.B - 1);
        const int bq = min(bbase + lane * 2 + 1, p.B - 1);
        fb[k] = make_float2(g_feat[(size_t)(i0 + oo + k) * p.B + ba],
                            g_feat[(size_t)(i0 + oo + k) * p.B + bq]);
      }
    }
    #pragma unroll
    for (int k = 0; k < 4; ++k) {
      const int i = i0 + oo + k;
      const float4 wa = wbase[i * 16 + g * 2];      // uniform, L1-hot
      const float4 wb = wbase[i * 16 + g * 2 + 1];
      const ull w0 = pack2(wa.x, wa.y);
      const ull w1v = pack2(wa.z, wa.w);
      const ull w2 = pack2(wb.x, wb.y);
      const ull w3 = pack2(wb.z, wb.w);
      const ull ff0 = pack2(fb[k].x, fb[k].x);
      const ull ff1 = pack2(fb[k].y, fb[k].y);
      acc[0][0] = fma2(ff0, w0, acc[0][0]);  acc[0][1] = fma2(ff1, w0, acc[0][1]);
      acc[1][0] = fma2(ff0, w1v, acc[1][0]); acc[1][1] = fma2(ff1, w1v, acc[1][1]);
      acc[2][0] = fma2(ff0, w2, acc[2][0]);  acc[2][1] = fma2(ff1, w2, acc[2][1]);
      acc[3][0] = fma2(ff0, w3, acc[3][0]);  acc[3][1] = fma2(ff1, w3, acc[3][1]);
    }
  }

  if (h == 1) {
    #pragma unroll
    for (int bi = 0; bi < 2; ++bi)
      #pragma unroll
      for (int cp = 0; cp < 4; ++cp) {
        float a, bb; unpack2(acc[cp][bi], a, bb);
        sP1[(lane * 2 + bi) * 65 + g * 8 + 2 * cp]     = a;
        sP1[(lane * 2 + bi) * 65 + g * 8 + 2 * cp + 1] = bb;
      }
  }
  __syncthreads();
  if (h == 0) {
    #pragma unroll
    for (int bi = 0; bi < 2; ++bi)
      #pragma unroll
      for (int cp = 0; cp < 4; ++cp) {
        float a, bb; unpack2(acc[cp][bi], a, bb);
        a  += sP1[(lane * 2 + bi) * 65 + g * 8 + 2 * cp];
        bb += sP1[(lane * 2 + bi) * 65 + g * 8 + 2 * cp + 1];
        sH[(lane * 2 + bi) * 65 + g * 8 + 2 * cp]     = 1.f / (1.f + __expf(-a));
        sH[(lane * 2 + bi) * 65 + g * 8 + 2 * cp + 1] = 1.f / (1.f + __expf(-bb));
      }
  }
  __syncthreads();

  if (tid < 64) {
    const int bgo = bbase + tid;
    if (bgo < p.B) {
      float o = p.lin2_b[0];
      #pragma unroll
      for (int j = 0; j < 64; ++j)
        o = fmaf(sH[tid * 65 + j], __ldg(p.lin2_w + j), o);
      p.out[bgo] = o;
    }
  }
}

} // namespace

extern "C" void kernel_launch(void* const* d_in, const int* in_sizes, int n_in,
                              void* d_out, int out_size) {
  ConvParams cp;
  for (int i = 0; i < 7; ++i) cp.seq[i] = (const float*)d_in[i];
  for (int j = 0; j < 5; ++j) cp.Wk[j] = (const float*)d_in[7 + j];
  cp.B = out_size;

  MlpParams mp;
  mp.lin1_w = (const float*)d_in[12];
  mp.lin1_b = (const float*)d_in[13];
  mp.lin2_w = (const float*)d_in[14];
  mp.lin2_b = (const float*)d_in[15];
  mp.out = (float*)d_out;
  mp.B   = out_size;

  static bool attr_set = false;
  if (!attr_set) {
    cudaFuncSetAttribute(conv_kernel,
                         cudaFuncAttributeMaxDynamicSharedMemorySize, CONV_SMEM_BYTES);
    cudaFuncSetAttribute(mlp_kernel,
                         cudaFuncAttributeMaxDynamicSharedMemorySize, MLP_SMEM_BYTES);
    attr_set = true;
  }

  const int tiles64 = (cp.B + 63) / 64;
  prep_kernel<<<(FEAT * 32 + 255) / 256, 256>>>(mp.lin1_w);
  dim3 cgrid(tiles64, 7);
  conv_kernel<<<cgrid, THREADS, CONV_SMEM_BYTES>>>(cp);
  mlp_kernel<<<tiles64, MTHREADS, MLP_SMEM_BYTES>>>(mp);
}

// round 12
// speedup vs baseline: 1.1350x; 1.0850x over previous
#include <cuda_runtime.h>
#include <cuda_fp16.h>
#include <math.h>

namespace {

constexpr int EMBED     = 20;
constexpr int THREADS   = 256;   // conv CTA
constexpr int FEAT      = 560;
constexpr int BATCH_MAX = 16384;

typedef unsigned long long ull;

// ---------------- packed f32x2 helpers (Blackwell FFMA2) ----------------
__device__ __forceinline__ ull pack2(float a, float b) {
  ull r;
  asm("mov.b64 %0, {%1, %2};" : "=l"(r) : "f"(a), "f"(b));
  return r;
}
__device__ __forceinline__ void unpack2(ull v, float& a, float& b) {
  asm("mov.b64 {%0, %1}, %2;" : "=f"(a), "=f"(b) : "l"(v));
}
__device__ __forceinline__ ull fma2(ull a, ull b, ull c) {
  ull d;
  asm("fma.rn.f32x2 %0, %1, %2, %3;" : "=l"(d) : "l"(a), "l"(b), "l"(c));
  return d;
}

// ---------------- global scratch ----------------
__device__ __half  g_feat[FEAT * BATCH_MAX];  // transposed [feat][B], fp16
__device__ float2  g_w1p[FEAT * 32];          // [i][colpair]

struct ConvParams {
  const float* seq[7];
  const float* Wk[5];
  int B;
};
struct MlpParams {
  const float* lin1_w;
  const float* lin1_b;
  const float* lin2_w;
  const float* lin2_b;
  float* out;
  int B;
};

// smem: x tile only, [c*L+l][33] float2 = (x_b, x_{b+32}); max L = 18
constexpr int CONV_SMEM_BYTES = EMBED * 18 * 33 * 8;   // 95040

// ========== conv chunk, BOTH filters of the warp's pair share x ==========
template<int L, int K, int T0, int T1>
__device__ __forceinline__ void conv_chunk2(const ull* __restrict__ sXu,
                                            const float* __restrict__ wg0,
                                            const float* __restrict__ wg1,
                                            int lane, float (&mx)[4]) {
  constexpr int PAD = (K - 1) / 2;
  constexpr int XLO = (T0 - PAD > 0) ? (T0 - PAD) : 0;
  constexpr int XHI = (T1 + PAD < L) ? (T1 + PAD) : L;   // exclusive
  constexpr int NX  = XHI - XLO;
  constexpr int NT  = T1 - T0;
  ull a0[NT], a1[NT];
  #pragma unroll
  for (int t = 0; t < NT; ++t) { a0[t] = 0ULL; a1[t] = 0ULL; }
  for (int c = 0; c < EMBED; ++c) {
    ull xx[NX];
    #pragma unroll
    for (int l = 0; l < NX; ++l)
      xx[l] = sXu[(c * L + XLO + l) * 33 + lane];        // LDS.64 once
    ull w0[K], w1[K];
    #pragma unroll
    for (int j = 0; j < K; ++j) {
      const float v0 = __ldg(wg0 + c * K + j);           // warp-uniform
      const float v1 = __ldg(wg1 + c * K + j);
      w0[j] = pack2(v0, v0);
      w1[j] = pack2(v1, v1);
    }
    #pragma unroll
    for (int t = T0; t < T1; ++t) {
      #pragma unroll
      for (int j = 0; j < K; ++j) {
        const int xi = t + j - PAD;                      // compile-time pred
        if (xi >= 0 && xi < L) {
          a0[t - T0] = fma2(xx[xi - XLO], w0[j], a0[t - T0]);
          a1[t - T0] = fma2(xx[xi - XLO], w1[j], a1[t - T0]);
        }
      }
    }
  }
  #pragma unroll
  for (int t = 0; t < NT; ++t) {
    float a, b;
    unpack2(a0[t], a, b); mx[0] = fmaxf(mx[0], a); mx[1] = fmaxf(mx[1], b);
    unpack2(a1[t], a, b); mx[2] = fmaxf(mx[2], a); mx[3] = fmaxf(mx[3], b);
  }
}

template<int L, int K>
__device__ __forceinline__ void conv_all2(const ull* __restrict__ sXu,
                                          const float* __restrict__ wg0,
                                          const float* __restrict__ wg1,
                                          int lane, float (&mx)[4]) {
  if constexpr (L <= 6) {
    conv_chunk2<L, K, 0, L>(sXu, wg0, wg1, lane, mx);
  } else if constexpr (L <= 9) {
    constexpr int M = (L + 1) / 2;
    conv_chunk2<L, K, 0, M>(sXu, wg0, wg1, lane, mx);
    conv_chunk2<L, K, M, L>(sXu, wg0, wg1, lane, mx);
  } else if constexpr (L <= 12) {
    conv_chunk2<L, K, 0, 6>(sXu, wg0, wg1, lane, mx);
    conv_chunk2<L, K, 6, L>(sXu, wg0, wg1, lane, mx);
  } else {
    conv_chunk2<L, K, 0, 6>(sXu, wg0, wg1, lane, mx);
    conv_chunk2<L, K, 6, 12>(sXu, wg0, wg1, lane, mx);
    conv_chunk2<L, K, 12, L>(sXu, wg0, wg1, lane, mx);
  }
}

template<int L, int S>
__device__ void do_seq(const ConvParams& p, float2* sX2,
                       int tid, int lane, int w, int bbase) {
  const float* xg = p.seq[S];
  constexpr int CL = EMBED * L;
  for (int idx = tid; idx < CL * 32; idx += THREADS) {
    const int bp  = idx / CL;
    const int rem = idx - bp * CL;
    const int b0  = min(bbase + bp, p.B - 1);
    const int b1  = min(b0 + 32, p.B - 1);
    sX2[rem * 33 + bp] = make_float2(xg[(size_t)b0 * CL + rem] * 0.2f,
                                     xg[(size_t)b1 * CL + rem] * 0.2f);
  }
  __syncthreads();
  const ull* sXu = (const ull*)sX2;
  const int bg0 = min(bbase + lane, p.B - 1);
  const int bg1 = min(bg0 + 32, p.B - 1);
  const int f0  = 2 * w;

  constexpr int KS_[5] = {1, 3, 5, 7, 9};
  #pragma unroll
  for (int kidx = 0; kidx < 5; ++kidx) {
    const int K = KS_[kidx];
    const float* wg0 = p.Wk[kidx] + ((size_t)S * 16 + f0) * EMBED * K;
    const float* wg1 = wg0 + EMBED * K;
    float mx[4];
    #pragma unroll
    for (int i = 0; i < 4; ++i) mx[i] = 0.f;   // relu folded into init
    switch (kidx) {   // K must be constexpr for templates
      case 0: conv_all2<L, 1>(sXu, wg0, wg1, lane, mx); break;
      case 1: conv_all2<L, 3>(sXu, wg0, wg1, lane, mx); break;
      case 2: conv_all2<L, 5>(sXu, wg0, wg1, lane, mx); break;
      case 3: conv_all2<L, 7>(sXu, wg0, wg1, lane, mx); break;
      case 4: conv_all2<L, 9>(sXu, wg0, wg1, lane, mx); break;
    }
    const int featBase = S * 80 + kidx * 16;
    g_feat[(size_t)(featBase + f0)     * p.B + bg0] = __float2half_rn(mx[0]);
    g_feat[(size_t)(featBase + f0)     * p.B + bg1] = __float2half_rn(mx[1]);
    g_feat[(size_t)(featBase + f0 + 1) * p.B + bg0] = __float2half_rn(mx[2]);
    g_feat[(size_t)(featBase + f0 + 1) * p.B + bg1] = __float2half_rn(mx[3]);
  }
}

__global__ __launch_bounds__(THREADS, 2) void conv_kernel(ConvParams p) {
  extern __shared__ float smem[];
  float2* sX2 = (float2*)smem;
  const int tid   = threadIdx.x;
  const int lane  = tid & 31;
  const int w     = tid >> 5;          // warp -> filter pair (2w, 2w+1)
  const int bbase = blockIdx.x * 64;   // 64 batch per CTA (paired)
  switch (blockIdx.y) {
    case 0: do_seq<12, 0>(p, sX2, tid, lane, w, bbase); break;
    case 1: do_seq< 7, 1>(p, sX2, tid, lane, w, bbase); break;
    case 2: do_seq< 8, 2>(p, sX2, tid, lane, w, bbase); break;
    case 3: do_seq<16, 3>(p, sX2, tid, lane, w, bbase); break;
    case 4: do_seq< 6, 4>(p, sX2, tid, lane, w, bbase); break;
    case 5: do_seq< 7, 5>(p, sX2, tid, lane, w, bbase); break;
    case 6: do_seq<18, 6>(p, sX2, tid, lane, w, bbase); break;
  }
}

// ---------------- prep: W1 pre-pack ----------------
__global__ void prep_kernel(const float* __restrict__ w1) {
  const int idx = blockIdx.x * 256 + threadIdx.x;
  if (idx < FEAT * 32) {
    const int i   = idx >> 5;
    const int col = idx & 31;
    g_w1p[idx] = make_float2(w1[(size_t)(2 * col) * FEAT + i],
                             w1[(size_t)(2 * col + 1) * FEAT + i]);
  }
}

// ====== MLP v8: v5 shape + fp16 features + 8-deep prefetch ===============
// 128 batch/CTA (grid 128), 512 thr; warp (h,g): h=feature half, g=8 cols.
// thread: 4 batch elems (half4 = uint2 feature loads).
constexpr int MTHREADS = 512;
constexpr int MLP_SMEM_BYTES = 2 * 128 * 65 * 4;   // 66560

__global__ __launch_bounds__(MTHREADS) void mlp_kernel(MlpParams p) {
  extern __shared__ float smem[];
  float* sP1 = smem;              // [128][65] h=1 partials
  float* sH  = smem + 128 * 65;   // [128][65] sigmoid outputs
  const int tid  = threadIdx.x;
  const int lane = tid & 31;
  const int wid  = tid >> 5;      // 0..15
  const int h    = wid >> 3;      // feature half
  const int g    = wid & 7;       // col group (cols 8g..8g+7)
  const int bbase = blockIdx.x * 128;
  const bool full = (bbase + 128 <= p.B);

  ull acc[4][4];                  // [colpair][batch elem]
  #pragma unroll
  for (int cp = 0; cp < 4; ++cp) {
    const ull bia = (h == 0)
      ? pack2(p.lin1_b[g * 8 + 2 * cp], p.lin1_b[g * 8 + 2 * cp + 1])
      : 0ULL;
    #pragma unroll
    for (int bi = 0; bi < 4; ++bi) acc[cp][bi] = bia;
  }

  const float4* wbase = (const float4*)(g_w1p);
  const int i0 = h * 280;
  const __half* fbase = g_feat + (size_t)i0 * p.B + bbase + lane * 4;

  for (int oo = 0; oo < 280; oo += 8) {
    uint2 fb[8];
    if (full) {
      #pragma unroll
      for (int k = 0; k < 8; ++k)
        fb[k] = __ldg((const uint2*)(fbase + (size_t)(oo + k) * p.B));
    } else {
      #pragma unroll
      for (int k = 0; k < 8; ++k) {
        __half v[4];
        #pragma unroll
        for (int bi = 0; bi < 4; ++bi) {
          const int b = min(bbase + lane * 4 + bi, p.B - 1);
          v[bi] = g_feat[(size_t)(i0 + oo + k) * p.B + b];
        }
        fb[k].x = ((unsigned)__half_as_ushort(v[1]) << 16) | __half_as_ushort(v[0]);
        fb[k].y = ((unsigned)__half_as_ushort(v[3]) << 16) | __half_as_ushort(v[2]);
      }
    }
    #pragma unroll
    for (int k = 0; k < 8; ++k) {
      const int i = i0 + oo + k;
      const float4 wa = wbase[i * 16 + g * 2];      // uniform, L1-hot
      const float4 wb = wbase[i * 16 + g * 2 + 1];
      const ull w0 = pack2(wa.x, wa.y);
      const ull w1v = pack2(wa.z, wa.w);
      const ull w2 = pack2(wb.x, wb.y);
      const ull w3 = pack2(wb.z, wb.w);
      const float2 flo = __half22float2(*(const __half2*)&fb[k].x);
      const float2 fhi = __half22float2(*(const __half2*)&fb[k].y);
      const float fv[4] = {flo.x, flo.y, fhi.x, fhi.y};
      #pragma unroll
      for (int bi = 0; bi < 4; ++bi) {
        const ull ff = pack2(fv[bi], fv[bi]);
        acc[0][bi] = fma2(ff, w0, acc[0][bi]);
        acc[1][bi] = fma2(ff, w1v, acc[1][bi]);
        acc[2][bi] = fma2(ff, w2, acc[2][bi]);
        acc[3][bi] = fma2(ff, w3, acc[3][bi]);
      }
    }
  }

  if (h == 1) {
    #pragma unroll
    for (int bi = 0; bi < 4; ++bi)
      #pragma unroll
      for (int cp = 0; cp < 4; ++cp) {
        float a, bb; unpack2(acc[cp][bi], a, bb);
        sP1[(lane * 4 + bi) * 65 + g * 8 + 2 * cp]     = a;
        sP1[(lane * 4 + bi) * 65 + g * 8 + 2 * cp + 1] = bb;
      }
  }
  __syncthreads();
  if (h == 0) {
    #pragma unroll
    for (int bi = 0; bi < 4; ++bi)
      #pragma unroll
      for (int cp = 0; cp < 4; ++cp) {
        float a, bb; unpack2(acc[cp][bi], a, bb);
        a  += sP1[(lane * 4 + bi) * 65 + g * 8 + 2 * cp];
        bb += sP1[(lane * 4 + bi) * 65 + g * 8 + 2 * cp + 1];
        sH[(lane * 4 + bi) * 65 + g * 8 + 2 * cp]     = 1.f / (1.f + __expf(-a));
        sH[(lane * 4 + bi) * 65 + g * 8 + 2 * cp + 1] = 1.f / (1.f + __expf(-bb));
      }
  }
  __syncthreads();

  if (tid < 128) {
    const int bgo = bbase + tid;
    if (bgo < p.B) {
      float o = p.lin2_b[0];
      #pragma unroll
      for (int j = 0; j < 64; ++j)
        o = fmaf(sH[tid * 65 + j], __ldg(p.lin2_w + j), o);
      p.out[bgo] = o;
    }
  }
}

} // namespace

extern "C" void kernel_launch(void* const* d_in, const int* in_sizes, int n_in,
                              void* d_out, int out_size) {
  ConvParams cp;
  for (int i = 0; i < 7; ++i) cp.seq[i] = (const float*)d_in[i];
  for (int j = 0; j < 5; ++j) cp.Wk[j] = (const float*)d_in[7 + j];
  cp.B = out_size;

  MlpParams mp;
  mp.lin1_w = (const float*)d_in[12];
  mp.lin1_b = (const float*)d_in[13];
  mp.lin2_w = (const float*)d_in[14];
  mp.lin2_b = (const float*)d_in[15];
  mp.out = (float*)d_out;
  mp.B   = out_size;

  static bool attr_set = false;
  if (!attr_set) {
    cudaFuncSetAttribute(conv_kernel,
                         cudaFuncAttributeMaxDynamicSharedMemorySize, CONV_SMEM_BYTES);
    cudaFuncSetAttribute(mlp_kernel,
                         cudaFuncAttributeMaxDynamicSharedMemorySize, MLP_SMEM_BYTES);
    attr_set = true;
  }

  const int tiles64  = (cp.B + 63) / 64;
  const int tiles128 = (cp.B + 127) / 128;
  prep_kernel<<<(FEAT * 32 + 255) / 256, 256>>>(mp.lin1_w);
  dim3 cgrid(tiles64, 7);
  conv_kernel<<<cgrid, THREADS, CONV_SMEM_BYTES>>>(cp);
  mlp_kernel<<<tiles128, MTHREADS, MLP_SMEM_BYTES>>>(mp);
}